// round 8
// baseline (speedup 1.0000x reference)
#include <cuda_runtime.h>
#include <cstdint>

// VectorQuantizer: single-pass TF32 mma.sync + provable margin flag + exact cleanup.
// inputs [131072, 64] f32, embeddings [512, 64] f32 (|e| <= 0.05 by construction)
// out (f32 buffer) = codes-as-float [131072] ++ code_vecs [131072*64]
//
// |dist_tf32 - dist_exact| <= 2^-9 * 0.05 * L1x  (tf32 rel err 2^-11 per operand).
// Rows with top-2 margin below 1.95e-4*L1x + 1e-3 are re-decided exactly with
// the R3/R7-validated fp32 arithmetic (lowest-index tie-break).

__device__ float vq_e2[512];
// B fragments (tf32): [nchunk 8][ntile 8][kpair 4][lane 32][comp 4]
__device__ __align__(16) uint32_t vq_bfrag[8 * 8 * 4 * 32 * 4];
__device__ int vq_nflag;
#define FLAG_CAP 131072
__device__ int vq_flags[FLAG_CAP];

__device__ __forceinline__ uint32_t f2tf32(float x) {
    uint32_t r;
    asm("cvt.rna.tf32.f32 %0, %1;" : "=r"(r) : "f"(x));
    return r;
}

__device__ __forceinline__ void mma8(float* d, const uint32_t* a,
                                     uint32_t b0, uint32_t b1) {
    asm volatile(
        "mma.sync.aligned.m16n8k8.row.col.f32.tf32.tf32.f32 "
        "{%0,%1,%2,%3}, {%4,%5,%6,%7}, {%8,%9}, {%0,%1,%2,%3};"
        : "+f"(d[0]), "+f"(d[1]), "+f"(d[2]), "+f"(d[3])
        : "r"(a[0]), "r"(a[1]), "r"(a[2]), "r"(a[3]), "r"(b0), "r"(b1));
}

// ---------------- prep: B fragments + e2 + flag reset ----------------
__global__ void vq_prep(const float* __restrict__ emb) {
    int blk = blockIdx.x, tid = threadIdx.x;
    if (blk < 128) {
        int id = blk * 256 + tid;          // 0..32767
        int n = id >> 6, k = id & 63;
        uint32_t t0 = f2tf32(emb[n * 64 + k]);
        int nc = n >> 6, nl = n & 63, nt = nl >> 3, g = nl & 7;
        int p = k >> 4, j = k & 3;
        int c = ((k >> 3) & 1) * 2 + ((k >> 2) & 1);
        int lane = g * 4 + j;
        vq_bfrag[(((nc * 8 + nt) * 4 + p) * 32 + lane) * 4 + c] = t0;
    } else {
        if (blk == 128 && tid == 0) vq_nflag = 0;   // reset every replay
        int code = (blk - 128) * 256 + tid;          // 0..511
        const float4* ep = (const float4*)(emb + code * 64);
        float s = 0.0f;
        #pragma unroll
        for (int q = 0; q < 16; ++q) {
            float4 v = ep[q];
            s += v.x * v.x + v.y * v.y + v.z * v.z + v.w * v.w;
        }
        vq_e2[code] = s;
    }
}

// ---------------- main (single-pass tf32) ----------------
#define AR 68   // A_raw row stride in floats (17 float4s: conflict-free)

__global__ __launch_bounds__(256, 2)
void vq_main(const float4* __restrict__ in4,    // [nrows][16]
             const float4* __restrict__ emb4,   // [512][16]
             float* __restrict__ codes_out,     // [nrows] (as float)
             float4* __restrict__ vecs_out)     // [nrows][16]
{
    __shared__ float A_raw[128 * AR];
    __shared__ float e2s[512];
    __shared__ float l2xs[128];
    __shared__ float l1xs[128];
    __shared__ int   rc[128];

    const int tid  = threadIdx.x;
    const int w    = tid >> 5;
    const int lane = tid & 31;
    const int g    = lane >> 2;
    const int j    = lane & 3;
    const int row0 = blockIdx.x * 128;

    #pragma unroll
    for (int i = 0; i < 8; ++i) {
        int item = i * 256 + tid;
        int r = item >> 4, seg = item & 15;
        *(float4*)&A_raw[r * AR + seg * 4] = in4[(size_t)(row0 + r) * 16 + seg];
    }
    #pragma unroll
    for (int i = 0; i < 2; ++i) e2s[tid + i * 256] = vq_e2[tid + i * 256];
    __syncthreads();

    if (tid < 128) {
        float s = 0.0f, s1 = 0.0f;
        #pragma unroll
        for (int q = 0; q < 16; ++q) {
            float4 v = *(const float4*)&A_raw[tid * AR + q * 4];
            s  += v.x * v.x + v.y * v.y + v.z * v.z + v.w * v.w;
            s1 += fabsf(v.x) + fabsf(v.y) + fabsf(v.z) + fabsf(v.w);
        }
        l2xs[tid] = s;
        l1xs[tid] = s1;
    }

    // A fragments (single tf32 pass): a[kstep 8][4]
    uint32_t a[8][4];
    {
        const int rlo = (w * 16 + g) * AR;
        const int rhi = (w * 16 + g + 8) * AR;
        #pragma unroll
        for (int kst = 0; kst < 8; ++kst) {
            a[kst][0] = f2tf32(A_raw[rlo + kst * 8 + j]);
            a[kst][1] = f2tf32(A_raw[rhi + kst * 8 + j]);
            a[kst][2] = f2tf32(A_raw[rlo + kst * 8 + j + 4]);
            a[kst][3] = f2tf32(A_raw[rhi + kst * 8 + j + 4]);
        }
    }
    __syncthreads();

    const float l2lo = l2xs[w * 16 + g];
    const float l2hi = l2xs[w * 16 + g + 8];
    float bdlo = 3.4e38f, bdhi = 3.4e38f;     // best
    float b2lo = 3.4e38f, b2hi = 3.4e38f;     // second best (value only)
    int   bilo = 0,       bihi = 0;

    const uint4* bf4 = (const uint4*)vq_bfrag;

    for (int nc = 0; nc < 8; ++nc) {
        float d[8][4];
        #pragma unroll
        for (int t = 0; t < 8; ++t)
            #pragma unroll
            for (int c = 0; c < 4; ++c) d[t][c] = 0.0f;

        const uint4* bc = bf4 + ((size_t)nc * 8) * 4 * 32;

        #pragma unroll
        for (int p = 0; p < 4; ++p) {
            #pragma unroll
            for (int ntg = 0; ntg < 2; ++ntg) {
                uint4 B0[4];
                #pragma unroll
                for (int q = 0; q < 4; ++q)
                    B0[q] = bc[((ntg * 4 + q) * 4 + p) * 32 + lane];
                #pragma unroll
                for (int q = 0; q < 4; ++q)
                    mma8(d[ntg * 4 + q], a[2 * p],     B0[q].x, B0[q].y);
                #pragma unroll
                for (int q = 0; q < 4; ++q)
                    mma8(d[ntg * 4 + q], a[2 * p + 1], B0[q].z, B0[q].w);
            }
        }

        #pragma unroll
        for (int nt = 0; nt < 8; ++nt) {
            int n0 = nc * 64 + nt * 8 + j * 2;
            float e0 = e2s[n0], e1 = e2s[n0 + 1];
            float t, dist;
            t = l2lo + e0; dist = fmaf(-2.0f, d[nt][0], t);
            if (dist < bdlo) { b2lo = bdlo; bdlo = dist; bilo = n0; }
            else if (dist < b2lo) b2lo = dist;
            t = l2lo + e1; dist = fmaf(-2.0f, d[nt][1], t);
            if (dist < bdlo) { b2lo = bdlo; bdlo = dist; bilo = n0 + 1; }
            else if (dist < b2lo) b2lo = dist;
            t = l2hi + e0; dist = fmaf(-2.0f, d[nt][2], t);
            if (dist < bdhi) { b2hi = bdhi; bdhi = dist; bihi = n0; }
            else if (dist < b2hi) b2hi = dist;
            t = l2hi + e1; dist = fmaf(-2.0f, d[nt][3], t);
            if (dist < bdhi) { b2hi = bdhi; bdhi = dist; bihi = n0 + 1; }
            else if (dist < b2hi) b2hi = dist;
        }
    }

    // reduce across the 4 j-lanes: (best,index) + second-best value
    #pragma unroll
    for (int off = 1; off <= 2; off <<= 1) {
        float o1, o2; int oi;
        o1 = __shfl_xor_sync(0xFFFFFFFFu, bdlo, off);
        oi = __shfl_xor_sync(0xFFFFFFFFu, bilo, off);
        o2 = __shfl_xor_sync(0xFFFFFFFFu, b2lo, off);
        b2lo = fminf(fminf(b2lo, o2), fmaxf(bdlo, o1));
        if (o1 < bdlo || (o1 == bdlo && oi < bilo)) { bdlo = o1; bilo = oi; }
        o1 = __shfl_xor_sync(0xFFFFFFFFu, bdhi, off);
        oi = __shfl_xor_sync(0xFFFFFFFFu, bihi, off);
        o2 = __shfl_xor_sync(0xFFFFFFFFu, b2hi, off);
        b2hi = fminf(fminf(b2hi, o2), fmaxf(bdhi, o1));
        if (o1 < bdhi || (o1 == bdhi && oi < bihi)) { bdhi = o1; bihi = oi; }
    }
    if (j == 0) {
        int rlo = w * 16 + g, rhi = rlo + 8;
        rc[rlo] = bilo;  codes_out[row0 + rlo] = (float)bilo;
        rc[rhi] = bihi;  codes_out[row0 + rhi] = (float)bihi;
        // provable margin bound: 2E + slack, E = 2^-10 * 0.05 * L1x * 2
        float thrlo = 1.953125e-4f * l1xs[rlo] + 1e-3f;
        float thrhi = 1.953125e-4f * l1xs[rhi] + 1e-3f;
        if (b2lo - bdlo < thrlo) {
            int s = atomicAdd(&vq_nflag, 1);
            if (s < FLAG_CAP) vq_flags[s] = row0 + rlo;
        }
        if (b2hi - bdhi < thrhi) {
            int s = atomicAdd(&vq_nflag, 1);
            if (s < FLAG_CAP) vq_flags[s] = row0 + rhi;
        }
    }
    __syncthreads();

    #pragma unroll
    for (int i = 0; i < 8; ++i) {
        int item = i * 256 + tid;
        int r = item >> 4, seg = item & 15;
        vecs_out[(size_t)(row0 + r) * 16 + seg] = emb4[rc[r] * 16 + seg];
    }
}

// ---------------- cleanup: exact R3 arithmetic on flagged rows ----------------
__global__ __launch_bounds__(256)
void vq_cleanup(const float* __restrict__ in,
                const float* __restrict__ emb,
                float* __restrict__ codes_out,
                float4* __restrict__ vecs_out)
{
    __shared__ float xs[64];
    __shared__ float l2x_sh;
    __shared__ float rv[256];
    __shared__ int   ri[256];

    const int tid = threadIdx.x;
    int n = vq_nflag;
    if (n > FLAG_CAP) n = FLAG_CAP;

    for (int f = blockIdx.x; f < n; f += gridDim.x) {
        const int row = vq_flags[f];
        if (tid < 16)
            *(float4*)&xs[tid * 4] = ((const float4*)(in + (size_t)row * 64))[tid];
        __syncthreads();

        if (tid == 0) {
            float s = 0.0f;
            #pragma unroll
            for (int q = 0; q < 16; ++q) {
                float4 v = *(const float4*)&xs[q * 4];
                s += v.x * v.x + v.y * v.y + v.z * v.z + v.w * v.w;
            }
            l2x_sh = s;
        }
        __syncthreads();
        const float l2x = l2x_sh;

        float bv = 3.4e38f; int bi = 0;
        #pragma unroll
        for (int cc = 0; cc < 2; ++cc) {
            int c = tid + cc * 256;            // ascending per thread
            const float* e = emb + c * 64;
            float lo = 0.0f, hi = 0.0f;        // R3 f32x2-equivalent chains
            #pragma unroll
            for (int dsg = 0; dsg < 16; ++dsg) {
                lo = fmaf(xs[4 * dsg],     e[4 * dsg],     lo);
                hi = fmaf(xs[4 * dsg + 1], e[4 * dsg + 1], hi);
                lo = fmaf(xs[4 * dsg + 2], e[4 * dsg + 2], lo);
                hi = fmaf(xs[4 * dsg + 3], e[4 * dsg + 3], hi);
            }
            float s2 = lo + hi;
            float t  = l2x + vq_e2[c];
            float dist = t - 2.0f * s2;        // single rounding (2*s2 exact)
            if (dist < bv) { bv = dist; bi = c; }
        }
        rv[tid] = bv; ri[tid] = bi;
        __syncthreads();
        #pragma unroll
        for (int st = 128; st > 0; st >>= 1) {
            if (tid < st) {
                float ov = rv[tid + st]; int oi = ri[tid + st];
                if (ov < rv[tid] || (ov == rv[tid] && oi < ri[tid])) {
                    rv[tid] = ov; ri[tid] = oi;
                }
            }
            __syncthreads();
        }
        const int best = ri[0];
        if (tid == 0) codes_out[row] = (float)best;
        if (tid < 16)
            vecs_out[(size_t)row * 16 + tid] =
                ((const float4*)(emb + best * 64))[tid];
        __syncthreads();
    }
}

extern "C" void kernel_launch(void* const* d_in, const int* in_sizes, int n_in,
                              void* d_out, int out_size)
{
    const int nrows  = in_sizes[0] / 64;     // 131072
    const int ntiles = nrows / 128;          // 1024

    float*  codes = (float*)d_out;
    float4* vecs  = (float4*)((float*)d_out + nrows);

    vq_prep<<<130, 256>>>((const float*)d_in[1]);
    vq_main<<<ntiles, 256>>>(
        (const float4*)d_in[0],
        (const float4*)d_in[1],
        codes, vecs);
    vq_cleanup<<<1024, 256>>>(
        (const float*)d_in[0],
        (const float*)d_in[1],
        codes, vecs);
}

// round 9
// speedup vs baseline: 11.0725x; 11.0725x over previous
#include <cuda_runtime.h>
#include <cuda_fp16.h>
#include <cstdint>

// VectorQuantizer: fp16 2-split mma.sync m16n8k16 (3 products) + margin flag
// + exact cleanup (smem-cached codebook, R3-validated arithmetic).
// inputs [131072, 64] f32, embeddings [512, 64] f32
// out (f32) = codes-as-float [131072] ++ code_vecs [131072*64]

__device__ float vq_e2[512];
// B fragments: [ntile 64][kstep 4][lane 32] x uint4{g0b0,g0b1,g1b0,g1b1}
__device__ __align__(16) uint4 vq_bfrag[64 * 4 * 32];
__device__ int vq_nflag;
#define FLAG_CAP 131072
__device__ int vq_flags[FLAG_CAP];
#define THRESH 1e-4f

__device__ __forceinline__ uint32_t packh(float lo, float hi) {
    __half2 h = __halves2half2(__float2half_rn(lo), __float2half_rn(hi));
    return *reinterpret_cast<uint32_t*>(&h);
}
__device__ __forceinline__ float h2f(float v) {           // fp16 round-trip
    return __half2float(__float2half_rn(v));
}

__device__ __forceinline__ void mma16(float* d, const uint32_t* a,
                                      uint32_t b0, uint32_t b1) {
    asm volatile(
        "mma.sync.aligned.m16n8k16.row.col.f32.f16.f16.f32 "
        "{%0,%1,%2,%3}, {%4,%5,%6,%7}, {%8,%9}, {%0,%1,%2,%3};"
        : "+f"(d[0]), "+f"(d[1]), "+f"(d[2]), "+f"(d[3])
        : "r"(a[0]), "r"(a[1]), "r"(a[2]), "r"(a[3]), "r"(b0), "r"(b1));
}

// ---------------- prep: B fragments + e2 + flag reset ----------------
__global__ void vq_prep(const float* __restrict__ emb) {
    int blk = blockIdx.x, tid = threadIdx.x;
    if (blk < 32) {
        int id   = blk * 256 + tid;        // 0..8191 = [nt 64][ks 4][lane 32]
        int lane = id & 31;
        int ks   = (id >> 5) & 3;
        int nt   = id >> 7;
        int g = lane >> 2, j = lane & 3;
        int code = nt * 8 + g;
        int kb   = ks * 16 + 2 * j;
        const float* e = emb + code * 64;
        float e0 = e[kb], e1 = e[kb + 1], e2v = e[kb + 8], e3 = e[kb + 9];
        uint4 v;
        v.x = packh(h2f(e0), h2f(e1));                       // g0 b0
        v.y = packh(h2f(e2v), h2f(e3));                      // g0 b1
        v.z = packh(h2f(e0 - h2f(e0)),  h2f(e1 - h2f(e1)));  // g1 b0
        v.w = packh(h2f(e2v - h2f(e2v)), h2f(e3 - h2f(e3))); // g1 b1
        vq_bfrag[(nt * 4 + ks) * 32 + lane] = v;
    } else {
        if (blk == 32 && tid == 0) vq_nflag = 0;   // reset every replay
        int code = (blk - 32) * 256 + tid;          // 0..511
        const float4* ep = (const float4*)(emb + code * 64);
        float s = 0.0f;
        #pragma unroll
        for (int q = 0; q < 16; ++q) {
            float4 v = ep[q];
            s += v.x * v.x + v.y * v.y + v.z * v.z + v.w * v.w;
        }
        vq_e2[code] = s;
    }
}

// ---------------- main ----------------
#define AR 68   // A_raw row stride in floats

__global__ __launch_bounds__(256, 2)
void vq_main(const float4* __restrict__ in4,    // [nrows][16]
             const float4* __restrict__ emb4,   // [512][16]
             float* __restrict__ codes_out,     // [nrows] (as float)
             float4* __restrict__ vecs_out)     // [nrows][16]
{
    __shared__ float A_raw[128 * AR];
    __shared__ float e2s[512];
    __shared__ float l2xs[128];
    __shared__ int   rc[128];

    const int tid  = threadIdx.x;
    const int w    = tid >> 5;
    const int lane = tid & 31;
    const int g    = lane >> 2;
    const int j    = lane & 3;
    const int row0 = blockIdx.x * 128;

    #pragma unroll
    for (int i = 0; i < 8; ++i) {
        int item = i * 256 + tid;
        int r = item >> 4, seg = item & 15;
        *(float4*)&A_raw[r * AR + seg * 4] = in4[(size_t)(row0 + r) * 16 + seg];
    }
    #pragma unroll
    for (int i = 0; i < 2; ++i) e2s[tid + i * 256] = vq_e2[tid + i * 256];
    __syncthreads();

    if (tid < 128) {
        float s = 0.0f;
        #pragma unroll
        for (int q = 0; q < 16; ++q) {
            float4 v = *(const float4*)&A_raw[tid * AR + q * 4];
            s += v.x * v.x + v.y * v.y + v.z * v.z + v.w * v.w;
        }
        l2xs[tid] = s;
    }

    // A fragments: ah0/ah1 [kstep 4][4 regs], fp16 2-split
    uint32_t ah0[4][4], ah1[4][4];
    {
        const int rlo = (w * 16 + g) * AR;
        const int rhi = rlo + 8 * AR;
        #pragma unroll
        for (int ks = 0; ks < 4; ++ks) {
            int c = ks * 16 + 2 * j;
            float2 xa = *(const float2*)&A_raw[rlo + c];
            float2 xb = *(const float2*)&A_raw[rhi + c];
            float2 xc = *(const float2*)&A_raw[rlo + c + 8];
            float2 xd = *(const float2*)&A_raw[rhi + c + 8];
            ah0[ks][0] = packh(h2f(xa.x), h2f(xa.y));
            ah0[ks][1] = packh(h2f(xb.x), h2f(xb.y));
            ah0[ks][2] = packh(h2f(xc.x), h2f(xc.y));
            ah0[ks][3] = packh(h2f(xd.x), h2f(xd.y));
            ah1[ks][0] = packh(h2f(xa.x - h2f(xa.x)), h2f(xa.y - h2f(xa.y)));
            ah1[ks][1] = packh(h2f(xb.x - h2f(xb.x)), h2f(xb.y - h2f(xb.y)));
            ah1[ks][2] = packh(h2f(xc.x - h2f(xc.x)), h2f(xc.y - h2f(xc.y)));
            ah1[ks][3] = packh(h2f(xd.x - h2f(xd.x)), h2f(xd.y - h2f(xd.y)));
        }
    }
    __syncthreads();

    const float l2lo = l2xs[w * 16 + g];
    const float l2hi = l2xs[w * 16 + g + 8];
    float bdlo = 3.4e38f, bdhi = 3.4e38f;     // best
    float b2lo = 3.4e38f, b2hi = 3.4e38f;     // second-best value
    int   bilo = 0,       bihi = 0;

    // 32 tile-pairs over 64 n-tiles (ascending codes)
    for (int np = 0; np < 32; ++np) {
        const int t0 = np * 2, t1 = t0 + 1;
        float d0[4] = {0.f, 0.f, 0.f, 0.f};
        float d1[4] = {0.f, 0.f, 0.f, 0.f};
        #pragma unroll
        for (int ks = 0; ks < 4; ++ks) {
            uint4 B0 = vq_bfrag[(t0 * 4 + ks) * 32 + lane];
            uint4 B1 = vq_bfrag[(t1 * 4 + ks) * 32 + lane];
            mma16(d0, ah0[ks], B0.x, B0.y);   // h0 * g0
            mma16(d1, ah0[ks], B1.x, B1.y);
            mma16(d0, ah0[ks], B0.z, B0.w);   // h0 * g1
            mma16(d1, ah0[ks], B1.z, B1.w);
            mma16(d0, ah1[ks], B0.x, B0.y);   // h1 * g0
            mma16(d1, ah1[ks], B1.x, B1.y);
        }
        #pragma unroll
        for (int half = 0; half < 2; ++half) {
            const float* d = half ? d1 : d0;
            const int c0 = (half ? t1 : t0) * 8 + 2 * j;
            float e0 = e2s[c0], e1 = e2s[c0 + 1];
            float t, dist;
            t = l2lo + e0; dist = fmaf(-2.0f, d[0], t);
            if (dist < bdlo) { b2lo = bdlo; bdlo = dist; bilo = c0; }
            else if (dist < b2lo) b2lo = dist;
            t = l2lo + e1; dist = fmaf(-2.0f, d[1], t);
            if (dist < bdlo) { b2lo = bdlo; bdlo = dist; bilo = c0 + 1; }
            else if (dist < b2lo) b2lo = dist;
            t = l2hi + e0; dist = fmaf(-2.0f, d[2], t);
            if (dist < bdhi) { b2hi = bdhi; bdhi = dist; bihi = c0; }
            else if (dist < b2hi) b2hi = dist;
            t = l2hi + e1; dist = fmaf(-2.0f, d[3], t);
            if (dist < bdhi) { b2hi = bdhi; bdhi = dist; bihi = c0 + 1; }
            else if (dist < b2hi) b2hi = dist;
        }
    }

    // reduce across the 4 j-lanes: (best,index) + second-best value
    #pragma unroll
    for (int off = 1; off <= 2; off <<= 1) {
        float o1, o2; int oi;
        o1 = __shfl_xor_sync(0xFFFFFFFFu, bdlo, off);
        oi = __shfl_xor_sync(0xFFFFFFFFu, bilo, off);
        o2 = __shfl_xor_sync(0xFFFFFFFFu, b2lo, off);
        b2lo = fminf(fminf(b2lo, o2), fmaxf(bdlo, o1));
        if (o1 < bdlo || (o1 == bdlo && oi < bilo)) { bdlo = o1; bilo = oi; }
        o1 = __shfl_xor_sync(0xFFFFFFFFu, bdhi, off);
        oi = __shfl_xor_sync(0xFFFFFFFFu, bihi, off);
        o2 = __shfl_xor_sync(0xFFFFFFFFu, b2hi, off);
        b2hi = fminf(fminf(b2hi, o2), fmaxf(bdhi, o1));
        if (o1 < bdhi || (o1 == bdhi && oi < bihi)) { bdhi = o1; bihi = oi; }
    }
    if (j == 0) {
        int rlo = w * 16 + g, rhi = rlo + 8;
        rc[rlo] = bilo;  codes_out[row0 + rlo] = (float)bilo;
        rc[rhi] = bihi;  codes_out[row0 + rhi] = (float)bihi;
        if (b2lo - bdlo < THRESH) {
            int s = atomicAdd(&vq_nflag, 1);
            if (s < FLAG_CAP) vq_flags[s] = row0 + rlo;
        }
        if (b2hi - bdhi < THRESH) {
            int s = atomicAdd(&vq_nflag, 1);
            if (s < FLAG_CAP) vq_flags[s] = row0 + rhi;
        }
    }
    __syncthreads();

    #pragma unroll
    for (int i = 0; i < 8; ++i) {
        int item = i * 256 + tid;
        int r = item >> 4, seg = item & 15;
        vecs_out[(size_t)(row0 + r) * 16 + seg] = emb4[rc[r] * 16 + seg];
    }
}

// ---------------- cleanup: exact R3 arithmetic, smem-cached codebook ----------------
__global__ __launch_bounds__(256)
void vq_cleanup(const float* __restrict__ in,
                const float* __restrict__ emb,
                float* __restrict__ codes_out,
                float4* __restrict__ vecs_out)
{
    extern __shared__ float esm[];   // [64 k][512 c] transposed codebook
    __shared__ float xs[64];
    __shared__ float l2x_sh;
    __shared__ float rv[256];
    __shared__ int   ri[256];

    const int tid = threadIdx.x;

    // load codebook transposed: esm[k*512 + c] = emb[c*64 + k]
    for (int idx = tid; idx < 32768; idx += 256) {
        int c = idx >> 6, k = idx & 63;
        esm[k * 512 + c] = emb[idx];
    }
    __syncthreads();

    int n = vq_nflag;
    if (n > FLAG_CAP) n = FLAG_CAP;

    for (int f = blockIdx.x; f < n; f += gridDim.x) {
        const int row = vq_flags[f];
        if (tid < 16)
            *(float4*)&xs[tid * 4] = ((const float4*)(in + (size_t)row * 64))[tid];
        __syncthreads();

        if (tid == 0) {
            float s = 0.0f;
            #pragma unroll
            for (int q = 0; q < 16; ++q) {
                float4 v = *(const float4*)&xs[q * 4];
                s += v.x * v.x + v.y * v.y + v.z * v.z + v.w * v.w;
            }
            l2x_sh = s;
        }
        __syncthreads();
        const float l2x = l2x_sh;

        float bv = 3.4e38f; int bi = 0;
        #pragma unroll
        for (int cc = 0; cc < 2; ++cc) {
            int c = tid + cc * 256;            // ascending per thread
            float lo = 0.0f, hi = 0.0f;        // R3 f32x2-equivalent chains
            #pragma unroll
            for (int dsg = 0; dsg < 16; ++dsg) {
                lo = fmaf(xs[4 * dsg],     esm[(4 * dsg) * 512 + c],     lo);
                hi = fmaf(xs[4 * dsg + 1], esm[(4 * dsg + 1) * 512 + c], hi);
                lo = fmaf(xs[4 * dsg + 2], esm[(4 * dsg + 2) * 512 + c], lo);
                hi = fmaf(xs[4 * dsg + 3], esm[(4 * dsg + 3) * 512 + c], hi);
            }
            float s2 = lo + hi;
            float t  = l2x + vq_e2[c];
            float dist = t - 2.0f * s2;        // single rounding (2*s2 exact)
            if (dist < bv) { bv = dist; bi = c; }
        }
        rv[tid] = bv; ri[tid] = bi;
        __syncthreads();
        #pragma unroll
        for (int st = 128; st > 0; st >>= 1) {
            if (tid < st) {
                float ov = rv[tid + st]; int oi = ri[tid + st];
                if (ov < rv[tid] || (ov == rv[tid] && oi < ri[tid])) {
                    rv[tid] = ov; ri[tid] = oi;
                }
            }
            __syncthreads();
        }
        const int best = ri[0];
        if (tid == 0) codes_out[row] = (float)best;
        if (tid < 16)
            vecs_out[(size_t)row * 16 + tid] =
                ((const float4*)(emb + best * 64))[tid];
        __syncthreads();
    }
}

extern "C" void kernel_launch(void* const* d_in, const int* in_sizes, int n_in,
                              void* d_out, int out_size)
{
    const int nrows  = in_sizes[0] / 64;     // 131072
    const int ntiles = nrows / 128;          // 1024

    float*  codes = (float*)d_out;
    float4* vecs  = (float4*)((float*)d_out + nrows);

    cudaFuncSetAttribute(vq_cleanup,
                         cudaFuncAttributeMaxDynamicSharedMemorySize,
                         32768 * 4);

    vq_prep<<<34, 256>>>((const float*)d_in[1]);
    vq_main<<<ntiles, 256>>>(
        (const float4*)d_in[0],
        (const float4*)d_in[1],
        codes, vecs);
    vq_cleanup<<<148, 256, 32768 * 4>>>(
        (const float*)d_in[0],
        (const float*)d_in[1],
        codes, vecs);
}

// round 10
// speedup vs baseline: 12.8648x; 1.1619x over previous
#include <cuda_runtime.h>
#include <cuda_fp16.h>
#include <cstdint>

// VectorQuantizer: fp16 2-split mma.sync m16n8k16 (3 products) + margin flag
// + exact cleanup (smem-cached codebook, R3-validated arithmetic).
// inputs [131072, 64] f32, embeddings [512, 64] f32
// out (f32) = codes-as-float [131072] ++ code_vecs [131072*64]
//
// Main-path score drops the per-row constant ||x||^2 (argmin-invariant);
// 4 accumulator tiles per iteration for HMMA latency hiding.

__device__ float vq_e2[512];
// B fragments: [ntile 64][kstep 4][lane 32] x uint4{g0b0,g0b1,g1b0,g1b1}
__device__ __align__(16) uint4 vq_bfrag[64 * 4 * 32];
__device__ int vq_nflag;
#define FLAG_CAP 131072
__device__ int vq_flags[FLAG_CAP];
#define THRESH 1e-4f

__device__ __forceinline__ uint32_t packh(float lo, float hi) {
    __half2 h = __halves2half2(__float2half_rn(lo), __float2half_rn(hi));
    return *reinterpret_cast<uint32_t*>(&h);
}
__device__ __forceinline__ float h2f(float v) {           // fp16 round-trip
    return __half2float(__float2half_rn(v));
}

__device__ __forceinline__ void mma16(float* d, const uint32_t* a,
                                      uint32_t b0, uint32_t b1) {
    asm volatile(
        "mma.sync.aligned.m16n8k16.row.col.f32.f16.f16.f32 "
        "{%0,%1,%2,%3}, {%4,%5,%6,%7}, {%8,%9}, {%0,%1,%2,%3};"
        : "+f"(d[0]), "+f"(d[1]), "+f"(d[2]), "+f"(d[3])
        : "r"(a[0]), "r"(a[1]), "r"(a[2]), "r"(a[3]), "r"(b0), "r"(b1));
}

// ---------------- prep: B fragments + e2 + flag reset ----------------
__global__ void vq_prep(const float* __restrict__ emb) {
    int blk = blockIdx.x, tid = threadIdx.x;
    if (blk < 32) {
        int id   = blk * 256 + tid;        // 0..8191 = [nt 64][ks 4][lane 32]
        int lane = id & 31;
        int ks   = (id >> 5) & 3;
        int nt   = id >> 7;
        int g = lane >> 2, j = lane & 3;
        int code = nt * 8 + g;
        int kb   = ks * 16 + 2 * j;
        const float* e = emb + code * 64;
        float e0 = e[kb], e1 = e[kb + 1], e2v = e[kb + 8], e3 = e[kb + 9];
        uint4 v;
        v.x = packh(h2f(e0), h2f(e1));                       // g0 b0
        v.y = packh(h2f(e2v), h2f(e3));                      // g0 b1
        v.z = packh(h2f(e0 - h2f(e0)),  h2f(e1 - h2f(e1)));  // g1 b0
        v.w = packh(h2f(e2v - h2f(e2v)), h2f(e3 - h2f(e3))); // g1 b1
        vq_bfrag[(nt * 4 + ks) * 32 + lane] = v;
    } else {
        if (blk == 32 && tid == 0) vq_nflag = 0;   // reset every replay
        int code = (blk - 32) * 256 + tid;          // 0..511
        const float4* ep = (const float4*)(emb + code * 64);
        float s = 0.0f;
        #pragma unroll
        for (int q = 0; q < 16; ++q) {
            float4 v = ep[q];
            s += v.x * v.x + v.y * v.y + v.z * v.z + v.w * v.w;
        }
        vq_e2[code] = s;
    }
}

// ---------------- main ----------------
#define AR 68   // A_raw row stride in floats

__global__ __launch_bounds__(256, 2)
void vq_main(const float4* __restrict__ in4,    // [nrows][16]
             const float4* __restrict__ emb4,   // [512][16]
             float* __restrict__ codes_out,     // [nrows] (as float)
             float4* __restrict__ vecs_out)     // [nrows][16]
{
    __shared__ float A_raw[128 * AR];
    __shared__ float e2s[512];
    __shared__ int   rc[128];

    const int tid  = threadIdx.x;
    const int w    = tid >> 5;
    const int lane = tid & 31;
    const int g    = lane >> 2;
    const int j    = lane & 3;
    const int row0 = blockIdx.x * 128;

    #pragma unroll
    for (int i = 0; i < 8; ++i) {
        int item = i * 256 + tid;
        int r = item >> 4, seg = item & 15;
        *(float4*)&A_raw[r * AR + seg * 4] = in4[(size_t)(row0 + r) * 16 + seg];
    }
    #pragma unroll
    for (int i = 0; i < 2; ++i) e2s[tid + i * 256] = vq_e2[tid + i * 256];
    __syncthreads();

    // A fragments: ah0/ah1 [kstep 4][4 regs], fp16 2-split
    uint32_t ah0[4][4], ah1[4][4];
    {
        const int rlo = (w * 16 + g) * AR;
        const int rhi = rlo + 8 * AR;
        #pragma unroll
        for (int ks = 0; ks < 4; ++ks) {
            int c = ks * 16 + 2 * j;
            float2 xa = *(const float2*)&A_raw[rlo + c];
            float2 xb = *(const float2*)&A_raw[rhi + c];
            float2 xc = *(const float2*)&A_raw[rlo + c + 8];
            float2 xd = *(const float2*)&A_raw[rhi + c + 8];
            ah0[ks][0] = packh(h2f(xa.x), h2f(xa.y));
            ah0[ks][1] = packh(h2f(xb.x), h2f(xb.y));
            ah0[ks][2] = packh(h2f(xc.x), h2f(xc.y));
            ah0[ks][3] = packh(h2f(xd.x), h2f(xd.y));
            ah1[ks][0] = packh(h2f(xa.x - h2f(xa.x)), h2f(xa.y - h2f(xa.y)));
            ah1[ks][1] = packh(h2f(xb.x - h2f(xb.x)), h2f(xb.y - h2f(xb.y)));
            ah1[ks][2] = packh(h2f(xc.x - h2f(xc.x)), h2f(xc.y - h2f(xc.y)));
            ah1[ks][3] = packh(h2f(xd.x - h2f(xd.x)), h2f(xd.y - h2f(xd.y)));
        }
    }

    // score = e2[c] - 2*dot  (||x||^2 dropped: per-row constant)
    float bdlo = 3.4e38f, bdhi = 3.4e38f;     // best
    float b2lo = 3.4e38f, b2hi = 3.4e38f;     // second-best value
    int   bilo = 0,       bihi = 0;

    // 16 quads over 64 n-tiles (ascending codes); 16 accumulators for ILP
    for (int nq = 0; nq < 16; ++nq) {
        const int t0 = nq * 4;
        float d[4][4];
        #pragma unroll
        for (int t = 0; t < 4; ++t)
            #pragma unroll
            for (int c = 0; c < 4; ++c) d[t][c] = 0.0f;

        #pragma unroll
        for (int ks = 0; ks < 4; ++ks) {
            uint4 B[4];
            #pragma unroll
            for (int t = 0; t < 4; ++t)
                B[t] = vq_bfrag[((t0 + t) * 4 + ks) * 32 + lane];
            #pragma unroll
            for (int t = 0; t < 4; ++t)       // h0 * g0
                mma16(d[t], ah0[ks], B[t].x, B[t].y);
            #pragma unroll
            for (int t = 0; t < 4; ++t)       // h0 * g1
                mma16(d[t], ah0[ks], B[t].z, B[t].w);
            #pragma unroll
            for (int t = 0; t < 4; ++t)       // h1 * g0
                mma16(d[t], ah1[ks], B[t].x, B[t].y);
        }

        #pragma unroll
        for (int t = 0; t < 4; ++t) {
            const int c0 = (t0 + t) * 8 + 2 * j;
            float e0 = e2s[c0], e1 = e2s[c0 + 1];
            float dist;
            dist = fmaf(-2.0f, d[t][0], e0);
            if (dist < bdlo) { b2lo = bdlo; bdlo = dist; bilo = c0; }
            else if (dist < b2lo) b2lo = dist;
            dist = fmaf(-2.0f, d[t][1], e1);
            if (dist < bdlo) { b2lo = bdlo; bdlo = dist; bilo = c0 + 1; }
            else if (dist < b2lo) b2lo = dist;
            dist = fmaf(-2.0f, d[t][2], e0);
            if (dist < bdhi) { b2hi = bdhi; bdhi = dist; bihi = c0; }
            else if (dist < b2hi) b2hi = dist;
            dist = fmaf(-2.0f, d[t][3], e1);
            if (dist < bdhi) { b2hi = bdhi; bdhi = dist; bihi = c0 + 1; }
            else if (dist < b2hi) b2hi = dist;
        }
    }

    // reduce across the 4 j-lanes: (best,index) + second-best value
    #pragma unroll
    for (int off = 1; off <= 2; off <<= 1) {
        float o1, o2; int oi;
        o1 = __shfl_xor_sync(0xFFFFFFFFu, bdlo, off);
        oi = __shfl_xor_sync(0xFFFFFFFFu, bilo, off);
        o2 = __shfl_xor_sync(0xFFFFFFFFu, b2lo, off);
        b2lo = fminf(fminf(b2lo, o2), fmaxf(bdlo, o1));
        if (o1 < bdlo || (o1 == bdlo && oi < bilo)) { bdlo = o1; bilo = oi; }
        o1 = __shfl_xor_sync(0xFFFFFFFFu, bdhi, off);
        oi = __shfl_xor_sync(0xFFFFFFFFu, bihi, off);
        o2 = __shfl_xor_sync(0xFFFFFFFFu, b2hi, off);
        b2hi = fminf(fminf(b2hi, o2), fmaxf(bdhi, o1));
        if (o1 < bdhi || (o1 == bdhi && oi < bihi)) { bdhi = o1; bihi = oi; }
    }
    if (j == 0) {
        int rlo = w * 16 + g, rhi = rlo + 8;
        rc[rlo] = bilo;  codes_out[row0 + rlo] = (float)bilo;
        rc[rhi] = bihi;  codes_out[row0 + rhi] = (float)bihi;
        if (b2lo - bdlo < THRESH) {
            int s = atomicAdd(&vq_nflag, 1);
            if (s < FLAG_CAP) vq_flags[s] = row0 + rlo;
        }
        if (b2hi - bdhi < THRESH) {
            int s = atomicAdd(&vq_nflag, 1);
            if (s < FLAG_CAP) vq_flags[s] = row0 + rhi;
        }
    }
    __syncthreads();

    #pragma unroll
    for (int i = 0; i < 8; ++i) {
        int item = i * 256 + tid;
        int r = item >> 4, seg = item & 15;
        vecs_out[(size_t)(row0 + r) * 16 + seg] = emb4[rc[r] * 16 + seg];
    }
}

// ---------------- cleanup: exact R3 arithmetic, smem-cached codebook ----------------
#define ES 520   // padded code stride per k-row (bank-conflict-free transpose)

__global__ __launch_bounds__(256)
void vq_cleanup(const float* __restrict__ in,
                const float* __restrict__ emb,
                float* __restrict__ codes_out,
                float4* __restrict__ vecs_out)
{
    extern __shared__ float esm[];   // [64 k][ES] transposed codebook
    __shared__ float xs[64];
    __shared__ float l2x_sh;
    __shared__ float rv[256];
    __shared__ int   ri[256];

    const int tid = threadIdx.x;

    // load codebook transposed: esm[k*ES + c] = emb[c*64 + k]
    for (int idx = tid; idx < 32768; idx += 256) {
        int c = idx >> 6, k = idx & 63;
        esm[k * ES + c] = emb[idx];
    }
    __syncthreads();

    int n = vq_nflag;
    if (n > FLAG_CAP) n = FLAG_CAP;

    for (int f = blockIdx.x; f < n; f += gridDim.x) {
        const int row = vq_flags[f];
        if (tid < 16)
            *(float4*)&xs[tid * 4] = ((const float4*)(in + (size_t)row * 64))[tid];
        __syncthreads();

        if (tid == 0) {
            float s = 0.0f;
            #pragma unroll
            for (int q = 0; q < 16; ++q) {
                float4 v = *(const float4*)&xs[q * 4];
                s += v.x * v.x + v.y * v.y + v.z * v.z + v.w * v.w;
            }
            l2x_sh = s;
        }
        __syncthreads();
        const float l2x = l2x_sh;

        float bv = 3.4e38f; int bi = 0;
        #pragma unroll
        for (int cc = 0; cc < 2; ++cc) {
            int c = tid + cc * 256;            // ascending per thread
            float lo = 0.0f, hi = 0.0f;        // R3 f32x2-equivalent chains
            #pragma unroll
            for (int dsg = 0; dsg < 16; ++dsg) {
                lo = fmaf(xs[4 * dsg],     esm[(4 * dsg) * ES + c],     lo);
                hi = fmaf(xs[4 * dsg + 1], esm[(4 * dsg + 1) * ES + c], hi);
                lo = fmaf(xs[4 * dsg + 2], esm[(4 * dsg + 2) * ES + c], lo);
                hi = fmaf(xs[4 * dsg + 3], esm[(4 * dsg + 3) * ES + c], hi);
            }
            float s2 = lo + hi;
            float t  = l2x + vq_e2[c];
            float dist = t - 2.0f * s2;        // single rounding (2*s2 exact)
            if (dist < bv) { bv = dist; bi = c; }
        }
        rv[tid] = bv; ri[tid] = bi;
        __syncthreads();
        #pragma unroll
        for (int st = 128; st > 0; st >>= 1) {
            if (tid < st) {
                float ov = rv[tid + st]; int oi = ri[tid + st];
                if (ov < rv[tid] || (ov == rv[tid] && oi < ri[tid])) {
                    rv[tid] = ov; ri[tid] = oi;
                }
            }
            __syncthreads();
        }
        const int best = ri[0];
        if (tid == 0) codes_out[row] = (float)best;
        if (tid < 16)
            vecs_out[(size_t)row * 16 + tid] =
                ((const float4*)(emb + best * 64))[tid];
        __syncthreads();
    }
}

extern "C" void kernel_launch(void* const* d_in, const int* in_sizes, int n_in,
                              void* d_out, int out_size)
{
    const int nrows  = in_sizes[0] / 64;     // 131072
    const int ntiles = nrows / 128;          // 1024

    float*  codes = (float*)d_out;
    float4* vecs  = (float4*)((float*)d_out + nrows);

    cudaFuncSetAttribute(vq_cleanup,
                         cudaFuncAttributeMaxDynamicSharedMemorySize,
                         64 * ES * 4);

    vq_prep<<<34, 256>>>((const float*)d_in[1]);
    vq_main<<<ntiles, 256>>>(
        (const float4*)d_in[0],
        (const float4*)d_in[1],
        codes, vecs);
    vq_cleanup<<<148, 256, 64 * ES * 4>>>(
        (const float*)d_in[0],
        (const float*)d_in[1],
        codes, vecs);
}

// round 11
// speedup vs baseline: 15.5228x; 1.2066x over previous
#include <cuda_runtime.h>
#include <cuda_fp16.h>
#include <cstdint>

// VectorQuantizer: 1-product fp16 mma.sync m16n8k16 + rigorous per-row margin
// flag + exact cleanup (codebook in registers, R3-validated f32x2 chains).
// inputs [131072, 64] f32, embeddings [512, 64] f32 (|e| < 0.05)
// out (f32) = codes-as-float [131072] ++ code_vecs [131072*64]
//
// dist_main = e2[c] - 2*(h0 . g0), h0 = fp16(x), g0 = fp16(e).
// |dist_main - dist_exact| <= 0.05*S|h1| + 2^-11*0.05*S|h0| (+ rounding slack)
// -> flag iff margin < 0.1*S|h1| + 4.883e-5*S|h0| + 1e-4.

__device__ float vq_e2[512];
__device__ __align__(16) uint2  vq_bfrag[64 * 4 * 32];     // g0 fragments
__device__ __align__(16) float2 vq_eT2[32 * 512];          // e pairs, transposed
__device__ int vq_nflag;
#define FLAG_CAP 131072
__device__ int vq_flags[FLAG_CAP];

__device__ __forceinline__ uint32_t packh(float lo, float hi) {
    __half2 h = __halves2half2(__float2half_rn(lo), __float2half_rn(hi));
    return *reinterpret_cast<uint32_t*>(&h);
}
__device__ __forceinline__ float h2f(float v) {
    return __half2float(__float2half_rn(v));
}
__device__ __forceinline__ void mma16(float* d, const uint32_t* a,
                                      uint32_t b0, uint32_t b1) {
    asm volatile(
        "mma.sync.aligned.m16n8k16.row.col.f32.f16.f16.f32 "
        "{%0,%1,%2,%3}, {%4,%5,%6,%7}, {%8,%9}, {%0,%1,%2,%3};"
        : "+f"(d[0]), "+f"(d[1]), "+f"(d[2]), "+f"(d[3])
        : "r"(a[0]), "r"(a[1]), "r"(a[2]), "r"(a[3]), "r"(b0), "r"(b1));
}
__device__ __forceinline__ void fma2(unsigned long long &acc,
                                     unsigned long long a,
                                     unsigned long long b) {
    asm("fma.rn.f32x2 %0, %1, %2, %0;" : "+l"(acc) : "l"(a), "l"(b));
}
__device__ __forceinline__ float2 unpack2(unsigned long long v) {
    float2 r;
    asm("mov.b64 {%0, %1}, %2;" : "=f"(r.x), "=f"(r.y) : "l"(v));
    return r;
}
__device__ __forceinline__ unsigned int ford(float f) {
    unsigned int u = __float_as_uint(f);
    return (u & 0x80000000u) ? ~u : (u | 0x80000000u);
}

// ---------------- prep: g0 fragments + e2 + eT2 + flag reset ----------------
__global__ void vq_prep(const float* __restrict__ emb) {
    int blk = blockIdx.x, tid = threadIdx.x;
    if (blk < 32) {
        int id   = blk * 256 + tid;        // [nt 64][ks 4][lane 32]
        int lane = id & 31;
        int ks   = (id >> 5) & 3;
        int nt   = id >> 7;
        int g = lane >> 2, j = lane & 3;
        int code = nt * 8 + g;
        int kb   = ks * 16 + 2 * j;
        const float* e = emb + code * 64;
        uint2 v;
        v.x = packh(h2f(e[kb]),     h2f(e[kb + 1]));
        v.y = packh(h2f(e[kb + 8]), h2f(e[kb + 9]));
        vq_bfrag[id] = v;
    } else if (blk < 34) {
        if (blk == 32 && tid == 0) vq_nflag = 0;   // reset every replay
        int code = (blk - 32) * 256 + tid;          // 0..511
        const float4* ep = (const float4*)(emb + code * 64);
        float s = 0.0f;
        #pragma unroll
        for (int q = 0; q < 16; ++q) {
            float4 v = ep[q];
            s += v.x * v.x + v.y * v.y + v.z * v.z + v.w * v.w;
        }
        vq_e2[code] = s;
    } else {
        int id = (blk - 34) * 256 + tid;   // 0..16383
        int c = id >> 5, kp = id & 31;
        vq_eT2[kp * 512 + c] =
            make_float2(emb[c * 64 + 2 * kp], emb[c * 64 + 2 * kp + 1]);
    }
}

// ---------------- main (1-product fp16) ----------------
#define AR 68   // A_raw row stride in floats

__global__ __launch_bounds__(256, 2)
void vq_main(const float4* __restrict__ in4,    // [nrows][16]
             const float4* __restrict__ emb4,   // [512][16]
             float* __restrict__ codes_out,     // [nrows] (as float)
             float4* __restrict__ vecs_out)     // [nrows][16]
{
    __shared__ float A_raw[128 * AR];
    __shared__ float e2s[512];
    __shared__ float thr[128];
    __shared__ int   rc[128];

    const int tid  = threadIdx.x;
    const int w    = tid >> 5;
    const int lane = tid & 31;
    const int g    = lane >> 2;
    const int j    = lane & 3;
    const int row0 = blockIdx.x * 128;

    #pragma unroll
    for (int i = 0; i < 8; ++i) {
        int item = i * 256 + tid;
        int r = item >> 4, seg = item & 15;
        *(float4*)&A_raw[r * AR + seg * 4] = in4[(size_t)(row0 + r) * 16 + seg];
    }
    #pragma unroll
    for (int i = 0; i < 2; ++i) e2s[tid + i * 256] = vq_e2[tid + i * 256];
    __syncthreads();

    // per-row rigorous threshold: 0.1*Sum|x-h0| + 4.883e-5*Sum|h0| + 1e-4
    if (tid < 128) {
        float s1h = 0.0f, s1h0 = 0.0f;
        #pragma unroll
        for (int q = 0; q < 16; ++q) {
            float4 v = *(const float4*)&A_raw[tid * AR + q * 4];
            float h;
            h = h2f(v.x); s1h0 += fabsf(h); s1h += fabsf(v.x - h);
            h = h2f(v.y); s1h0 += fabsf(h); s1h += fabsf(v.y - h);
            h = h2f(v.z); s1h0 += fabsf(h); s1h += fabsf(v.z - h);
            h = h2f(v.w); s1h0 += fabsf(h); s1h += fabsf(v.w - h);
        }
        thr[tid] = 0.1f * s1h + 4.8828125e-5f * s1h0 + 1e-4f;
    }

    // A fragments: ah0 [kstep 4][4 regs], single fp16 pass
    uint32_t ah0[4][4];
    {
        const int rlo = (w * 16 + g) * AR;
        const int rhi = rlo + 8 * AR;
        #pragma unroll
        for (int ks = 0; ks < 4; ++ks) {
            int c = ks * 16 + 2 * j;
            float2 xa = *(const float2*)&A_raw[rlo + c];
            float2 xb = *(const float2*)&A_raw[rhi + c];
            float2 xc = *(const float2*)&A_raw[rlo + c + 8];
            float2 xd = *(const float2*)&A_raw[rhi + c + 8];
            ah0[ks][0] = packh(h2f(xa.x), h2f(xa.y));
            ah0[ks][1] = packh(h2f(xb.x), h2f(xb.y));
            ah0[ks][2] = packh(h2f(xc.x), h2f(xc.y));
            ah0[ks][3] = packh(h2f(xd.x), h2f(xd.y));
        }
    }
    __syncthreads();   // thr[] ready

    float bdlo = 3.4e38f, bdhi = 3.4e38f;     // best
    float b2lo = 3.4e38f, b2hi = 3.4e38f;     // second-best value
    int   bilo = 0,       bihi = 0;

    for (int nq = 0; nq < 16; ++nq) {
        const int t0 = nq * 4;
        float d[4][4];
        #pragma unroll
        for (int t = 0; t < 4; ++t)
            #pragma unroll
            for (int c = 0; c < 4; ++c) d[t][c] = 0.0f;

        #pragma unroll
        for (int ks = 0; ks < 4; ++ks) {
            uint2 B[4];
            #pragma unroll
            for (int t = 0; t < 4; ++t)
                B[t] = vq_bfrag[((t0 + t) * 4 + ks) * 32 + lane];
            #pragma unroll
            for (int t = 0; t < 4; ++t)
                mma16(d[t], ah0[ks], B[t].x, B[t].y);   // h0 * g0
        }

        #pragma unroll
        for (int t = 0; t < 4; ++t) {
            const int c0 = (t0 + t) * 8 + 2 * j;
            float e0 = e2s[c0], e1 = e2s[c0 + 1];
            float dist;
            dist = fmaf(-2.0f, d[t][0], e0);
            if (dist < bdlo) { b2lo = bdlo; bdlo = dist; bilo = c0; }
            else if (dist < b2lo) b2lo = dist;
            dist = fmaf(-2.0f, d[t][1], e1);
            if (dist < bdlo) { b2lo = bdlo; bdlo = dist; bilo = c0 + 1; }
            else if (dist < b2lo) b2lo = dist;
            dist = fmaf(-2.0f, d[t][2], e0);
            if (dist < bdhi) { b2hi = bdhi; bdhi = dist; bihi = c0; }
            else if (dist < b2hi) b2hi = dist;
            dist = fmaf(-2.0f, d[t][3], e1);
            if (dist < bdhi) { b2hi = bdhi; bdhi = dist; bihi = c0 + 1; }
            else if (dist < b2hi) b2hi = dist;
        }
    }

    #pragma unroll
    for (int off = 1; off <= 2; off <<= 1) {
        float o1, o2; int oi;
        o1 = __shfl_xor_sync(0xFFFFFFFFu, bdlo, off);
        oi = __shfl_xor_sync(0xFFFFFFFFu, bilo, off);
        o2 = __shfl_xor_sync(0xFFFFFFFFu, b2lo, off);
        b2lo = fminf(fminf(b2lo, o2), fmaxf(bdlo, o1));
        if (o1 < bdlo || (o1 == bdlo && oi < bilo)) { bdlo = o1; bilo = oi; }
        o1 = __shfl_xor_sync(0xFFFFFFFFu, bdhi, off);
        oi = __shfl_xor_sync(0xFFFFFFFFu, bihi, off);
        o2 = __shfl_xor_sync(0xFFFFFFFFu, b2hi, off);
        b2hi = fminf(fminf(b2hi, o2), fmaxf(bdhi, o1));
        if (o1 < bdhi || (o1 == bdhi && oi < bihi)) { bdhi = o1; bihi = oi; }
    }
    if (j == 0) {
        int rlo = w * 16 + g, rhi = rlo + 8;
        rc[rlo] = bilo;  codes_out[row0 + rlo] = (float)bilo;
        rc[rhi] = bihi;  codes_out[row0 + rhi] = (float)bihi;
        if (b2lo - bdlo < thr[rlo]) {
            int s = atomicAdd(&vq_nflag, 1);
            if (s < FLAG_CAP) vq_flags[s] = row0 + rlo;
        }
        if (b2hi - bdhi < thr[rhi]) {
            int s = atomicAdd(&vq_nflag, 1);
            if (s < FLAG_CAP) vq_flags[s] = row0 + rhi;
        }
    }
    __syncthreads();

    #pragma unroll
    for (int i = 0; i < 8; ++i) {
        int item = i * 256 + tid;
        int r = item >> 4, seg = item & 15;
        vecs_out[(size_t)(row0 + r) * 16 + seg] = emb4[rc[r] * 16 + seg];
    }
}

// ------- cleanup: exact R3 arithmetic, codebook in registers, 32-row batches -------
__global__ __launch_bounds__(512, 1)
void vq_cleanup(const float* __restrict__ in,
                const float4* __restrict__ emb4,
                float* __restrict__ codes_out,
                float4* __restrict__ vecs_out)
{
    __shared__ float xs[32 * 64];
    __shared__ float l2xr[32];
    __shared__ unsigned long long wred[32][16];
    __shared__ int widx[32];

    const int tid  = threadIdx.x;   // == code 0..511
    const int lane = tid & 31;
    const int wid  = tid >> 5;

    // codebook column c=tid in registers: 32 packed (even,odd) f32 pairs
    unsigned long long ereg[32];
    #pragma unroll
    for (int kp = 0; kp < 32; ++kp) {
        float2 ev = vq_eT2[kp * 512 + tid];
        asm("mov.b64 %0, {%1, %2};" : "=l"(ereg[kp]) : "f"(ev.x), "f"(ev.y));
    }
    const float myE2 = vq_e2[tid];

    int n = vq_nflag;
    if (n > FLAG_CAP) n = FLAG_CAP;
    const int nbatch = (n + 31) >> 5;

    for (int b = blockIdx.x; b < nbatch; b += gridDim.x) {
        const int base = b * 32;
        const int cnt  = min(32, n - base);

        if (tid < cnt * 16) {
            int r = tid >> 4, seg = tid & 15;
            int row = vq_flags[base + r];
            *(float4*)&xs[r * 64 + seg * 4] =
                ((const float4*)in)[(size_t)row * 16 + seg];
        }
        __syncthreads();
        if (tid < cnt) {
            float s = 0.0f;
            #pragma unroll
            for (int q = 0; q < 16; ++q) {
                float4 v = *(const float4*)&xs[tid * 64 + q * 4];
                s += v.x * v.x + v.y * v.y + v.z * v.z + v.w * v.w;
            }
            l2xr[tid] = s;
        }
        __syncthreads();

        for (int r = 0; r < cnt; ++r) {
            const unsigned long long* x2 =
                (const unsigned long long*)&xs[r * 64];
            unsigned long long acc = 0ull;   // (even-chain, odd-chain)
            #pragma unroll
            for (int kp = 0; kp < 32; ++kp) fma2(acc, x2[kp], ereg[kp]);
            float2 p = unpack2(acc);
            float s2 = p.x + p.y;
            float t  = l2xr[r] + myE2;
            float dist = t - 2.0f * s2;      // single rounding (2*s2 exact)
            unsigned long long pk =
                ((unsigned long long)ford(dist) << 32) | (unsigned)tid;
            #pragma unroll
            for (int o = 16; o > 0; o >>= 1) {
                unsigned long long ot = __shfl_xor_sync(0xFFFFFFFFu, pk, o);
                pk = (ot < pk) ? ot : pk;
            }
            if (lane == 0) wred[r][wid] = pk;
        }
        __syncthreads();

        if (tid < cnt) {
            unsigned long long m = wred[tid][0];
            #pragma unroll
            for (int q = 1; q < 16; ++q)
                m = (wred[tid][q] < m) ? wred[tid][q] : m;
            int idx = (int)(m & 0xFFFFFFFFull);
            widx[tid] = idx;
            codes_out[vq_flags[base + tid]] = (float)idx;
        }
        __syncthreads();
        if (tid < cnt * 16) {
            int r = tid >> 4, seg = tid & 15;
            int row = vq_flags[base + r];
            vecs_out[(size_t)row * 16 + seg] = emb4[widx[r] * 16 + seg];
        }
        __syncthreads();
    }
}

extern "C" void kernel_launch(void* const* d_in, const int* in_sizes, int n_in,
                              void* d_out, int out_size)
{
    const int nrows  = in_sizes[0] / 64;     // 131072
    const int ntiles = nrows / 128;          // 1024

    float*  codes = (float*)d_out;
    float4* vecs  = (float4*)((float*)d_out + nrows);

    vq_prep<<<98, 256>>>((const float*)d_in[1]);
    vq_main<<<ntiles, 256>>>(
        (const float4*)d_in[0],
        (const float4*)d_in[1],
        codes, vecs);
    vq_cleanup<<<148, 512>>>(
        (const float*)d_in[0],
        (const float4*)d_in[1],
        codes, vecs);
}